// round 16
// baseline (speedup 1.0000x reference)
#include <cuda_runtime.h>
#include <cuda_bf16.h>

#define NBATCH 256
#define LSEQ   4096
#define KER    15
#define LOUT   (LSEQ - KER + 1)   // 4082
#define DL     64
#define DC     128
#define NIV    (KER * 4)          // 60
#define NTHR   512

// ---------------- device scratch (rewritten every launch) ----------------
__device__ __align__(16) float g_Wc[NIV * DC];     // Wc[iv][c]
__device__ __align__(16) float g_U[NIV * DC];      // isq * Wc * Wk^T
__device__ __align__(16) float g_V[NIV * DC];      // (Wc * Wq^T) / LOUT
__device__ __align__(16) float g_WvWc[DC * NIV];   // Wv * Wc^T
__device__ __align__(16) float g_w[DC];            // bq + Wq*conv_b
__device__ __align__(16) float g_ob[DC];           // bv + Wv*conv_b

// ---------------- software grid barrier (sense-reversing) ----------------
__device__ unsigned g_barc = 0;
__device__ volatile unsigned g_sense = 0;

__device__ __forceinline__ void grid_barrier(int tid) {
    __syncthreads();
    if (tid == 0) {
        unsigned s = g_sense;
        __threadfence();
        unsigned old = atomicAdd(&g_barc, 1u);
        if (old == NBATCH - 1) {
            g_barc = 0;
            __threadfence();
            g_sense = s ^ 1u;
        } else {
            while (g_sense == s) { }
        }
        __threadfence();
    }
    __syncthreads();
}

#define FOR15(F) F(0) F(1) F(2) F(3) F(4) F(5) F(6) F(7) F(8) F(9) F(10) F(11) F(12) F(13) F(14)

// 256 blocks x 512 threads, <=64 regs, ~81KB smem => 2 blocks/SM => 296 >= 256 co-resident.
__global__ void __launch_bounds__(NTHR, 2)
seq_all(const int*   __restrict__ tokens,
        const float* __restrict__ emb,   const float* __restrict__ conv_w,
        const float* __restrict__ conv_b,
        const float* __restrict__ Wq,    const float* __restrict__ bq,
        const float* __restrict__ Wk,    const float* __restrict__ Wv,
        const float* __restrict__ bv,    float* __restrict__ out) {
    extern __shared__ float dynsh[];
    float* Tbl = dynsh;                 // [3072] chunk tables / setup scratch
    // LUT: entry k of thread tid at dynsh[3072 + k*NTHR + tid] -> bank = tid%32 ALWAYS
    float* lutb = dynsh + 3072 + threadIdx.x;

    __shared__ unsigned int Xs[131], Ys[131];   // 128 words + 3 zero guards
    __shared__ float t_s[DC];
    __shared__ float S_s[NIV], fcnt_s[NIV], A_s[NIV];
    __shared__ float wacc[16][48];
    __shared__ float fin[46];           // [0..14]=Ex, [15..29]=Ey, [30..44]=Exy, [45]=E
    __shared__ int hist_s[4];
    __shared__ float bmax_s;

    const int tid = threadIdx.x, lane = tid & 31, warp = tid >> 5;
    const int bid = blockIdx.x;
    float* scratch = Tbl;

    if (tid < 4) hist_s[tid] = 0;
    if (tid == 0) { Xs[128] = Xs[129] = Xs[130] = 0u;
                    Ys[128] = Ys[129] = Ys[130] = 0u; }
    __syncthreads();

    // ======== prologue: tokens -> bitplanes + histogram ========
    {
        const int* trow = tokens + (size_t)bid * LSEQ;
        int n0 = 0, n1 = 0, n2 = 0, n3 = 0;
#pragma unroll
        for (int m = 0; m < 8; m++) {
            int t = trow[m * NTHR + warp * 32 + lane];
            unsigned b0 = __ballot_sync(0xffffffffu, t & 1);
            unsigned b1 = __ballot_sync(0xffffffffu, t & 2);
            if (lane == 0) {
                Xs[m * 16 + warp] = b0; Ys[m * 16 + warp] = b1;
                int c3 = __popc(b0 & b1);
                int c1 = __popc(b0) - c3;
                int c2 = __popc(b1) - c3;
                n3 += c3; n1 += c1; n2 += c2; n0 += 32 - c1 - c2 - c3;
            }
        }
        if (lane == 0) {
            atomicAdd(&hist_s[0], n0); atomicAdd(&hist_s[1], n1);
            atomicAdd(&hist_s[2], n2); atomicAdd(&hist_s[3], n3);
        }
    }
    __syncthreads();

#define TOK_AT(p) ((int)(((Xs[(p) >> 5] >> ((p) & 31)) & 1u) | (((Ys[(p) >> 5] >> ((p) & 31)) & 1u) << 1)))

    if (tid < NIV) {   // sliding-window counts
        int i = tid >> 2, v = tid & 3;
        int cnt = hist_s[v];
        for (int p = 0; p < i; p++) cnt -= (TOK_AT(p) == v);
        for (int p = i + LOUT; p < LSEQ; p++) cnt -= (TOK_AT(p) == v);
        fcnt_s[tid] = (float)cnt;
    }

    // ======== setup phase 1 (blocks 0..127): Wc column c=bid ========
    if (bid < DC) {
        float* cw   = scratch;          // 960 floats (coalesced stage)
        float* embS = scratch + 960;    // 256
        for (int idx = tid; idx < DL * KER; idx += NTHR) cw[idx] = conv_w[bid * (DL * KER) + idx];
        for (int idx = tid; idx < 4 * DL;  idx += NTHR) embS[idx] = emb[idx];
        __syncthreads();
        if (tid < NIV) {
            int i = tid >> 2, v = tid & 3;
            float s = 0.f;
#pragma unroll 16
            for (int d = 0; d < DL; d++) s += embS[v * DL + d] * cw[d * KER + i];
            g_Wc[tid * DC + bid] = s;
        }
    }

    grid_barrier(tid);   // g_Wc complete

    // ======== setup phase 2 (blocks 0..127): U, V, WvWc, w, ob ========
    if (bid < DC) {
        float* wkS = scratch;          float* wqS = scratch + DC;
        float* wvS = scratch + 2 * DC; float* cbS = scratch + 3 * DC;
        for (int idx = tid; idx < DC; idx += NTHR) {
            wkS[idx] = Wk[bid * DC + idx];
            wqS[idx] = Wq[bid * DC + idx];
            wvS[idx] = Wv[bid * DC + idx];
            cbS[idx] = conv_b[idx];
        }
        __syncthreads();
        const float isq = 0.088388347648318447f;  // 1/sqrt(128)
        if (tid < NIV) {
            const float4* wc4 = (const float4*)(g_Wc + tid * DC);
            float su = 0.f, sv = 0.f, sw = 0.f;
#pragma unroll 8
            for (int q = 0; q < DC / 4; q++) {
                float4 f = wc4[q];
                int d = q * 4;
                su += f.x * wkS[d] + f.y * wkS[d + 1] + f.z * wkS[d + 2] + f.w * wkS[d + 3];
                sv += f.x * wqS[d] + f.y * wqS[d + 1] + f.z * wqS[d + 2] + f.w * wqS[d + 3];
                sw += f.x * wvS[d] + f.y * wvS[d + 1] + f.z * wvS[d + 2] + f.w * wvS[d + 3];
            }
            g_U[tid * DC + bid] = su * isq;
            g_V[tid * DC + bid] = sv * (1.0f / (float)LOUT);
            g_WvWc[bid * NIV + tid] = sw;
        } else if (tid == 60) {
            float s = bq[bid];
#pragma unroll 8
            for (int e = 0; e < DC; e++) s += wqS[e] * cbS[e];
            g_w[bid] = s;
        } else if (tid == 61) {
            float s = bv[bid];
#pragma unroll 8
            for (int e = 0; e < DC; e++) s += wvS[e] * cbS[e];
            g_ob[bid] = s;
        }
    }

    grid_barrier(tid);   // setup complete

    // ======== per-batch score table: t = w + V'^T fcnt ; S = U' t ========
    if (tid < DC) {
        float s = g_w[tid];
#pragma unroll 12
        for (int j = 0; j < NIV; j++) s += g_V[j * DC + tid] * fcnt_s[j];
        t_s[tid] = s;
    }
    __syncthreads();
    if (tid < NIV) {
        const float4* u4 = (const float4*)(g_U + tid * DC);
        float s = 0.f;
#pragma unroll 8
        for (int q = 0; q < DC / 4; q++) {
            float4 f = u4[q];
            int e = q * 4;
            s += f.x * t_s[e] + f.y * t_s[e + 1] + f.z * t_s[e + 2] + f.w * t_s[e + 3];
        }
        S_s[tid] = s;
    }
    __syncthreads();

    // ======== chunk tables + per-chunk maxima (softmax shift bound) ========
    {
        float m0 = -1e30f, m1 = -1e30f, m2 = -1e30f;
#pragma unroll
        for (int q = 0; q < 6; q++) {
            int idx = tid + q * NTHR;
            int k = idx >> 10, u = idx & 1023;
            int xb = u & 31, yb = u >> 5;
            float s = 0.f;
#pragma unroll
            for (int j = 0; j < 5; j++) {
                int v = ((xb >> j) & 1) | (((yb >> j) & 1) << 1);
                s += S_s[(5 * k + j) * 4 + v];
            }
            Tbl[idx] = s;
            if (q < 2) m0 = fmaxf(m0, s);
            else if (q < 4) m1 = fmaxf(m1, s);
            else m2 = fmaxf(m2, s);
        }
#pragma unroll
        for (int o = 16; o > 0; o >>= 1) {
            m0 = fmaxf(m0, __shfl_xor_sync(0xffffffffu, m0, o));
            m1 = fmaxf(m1, __shfl_xor_sync(0xffffffffu, m1, o));
            m2 = fmaxf(m2, __shfl_xor_sync(0xffffffffu, m2, o));
        }
        if (lane == 0) { wacc[warp][0] = m0; wacc[warp][1] = m1; wacc[warp][2] = m2; }
        __syncthreads();
        if (tid == 0) {
            float a = wacc[0][0], b = wacc[0][1], c = wacc[0][2];
#pragma unroll
            for (int w = 1; w < 16; w++) {
                a = fmaxf(a, wacc[w][0]); b = fmaxf(b, wacc[w][1]); c = fmaxf(c, wacc[w][2]);
            }
            bmax_s = a + b + c;
        }
        __syncthreads();
    }
    const float bmax = bmax_s;

    // ======== window words: 8 consecutive positions per thread ========
    const int base = tid * 8;
    const int wi = base >> 5;
    const int sh0 = base & 31;    // 0,8,16,24 — pre-shift so tap shifts stay <= 14
    const unsigned xw0 = __funnelshift_r(Xs[wi],     Xs[wi + 1], sh0);
    const unsigned xw1 = __funnelshift_r(Xs[wi + 1], Xs[wi + 2], sh0);
    const unsigned yw0 = __funnelshift_r(Ys[wi],     Ys[wi + 1], sh0);
    const unsigned yw1 = __funnelshift_r(Ys[wi + 1], Ys[wi + 2], sh0);

    // ======== PASS A: e + 2 bank-aligned subset-sum LUTs ========
    float accE = 0.f;
#pragma unroll
    for (int g = 0; g < 2; g++) {
        float ev[4];
#pragma unroll
        for (int r = 0; r < 4; r++) {
            int j = g * 4 + r;
            unsigned bx = __funnelshift_r(xw0, xw1, j);
            unsigned by = __funnelshift_r(yw0, yw1, j);
            int u0 = (bx & 31) | ((by & 31) << 5);
            int u1 = ((bx >> 5) & 31) | (((by >> 5) & 31) << 5);
            int u2 = ((bx >> 10) & 31) | (((by >> 10) & 31) << 5);
            float s = Tbl[u0] + Tbl[1024 + u1] + Tbl[2048 + u2];
            float e = __expf(s - bmax);
            ev[r] = (base + j < LOUT) ? e : 0.f;
        }
        float l3  = ev[1] + ev[0];
        float l5  = ev[2] + ev[0];
        float l6  = ev[2] + ev[1];
        float l7  = ev[2] + l3;
        float l9  = ev[3] + ev[0];
        float l10 = ev[3] + ev[1];
        float l11 = ev[3] + l3;
        float l12 = ev[3] + ev[2];
        float l13 = ev[3] + l5;
        float l14 = ev[3] + l6;
        float l15 = ev[3] + l7;
        float* L = lutb + (g * 16) * NTHR;     // bank-aligned: stride NTHR per entry
        L[0] = 0.f;          L[1 * NTHR] = ev[0]; L[2 * NTHR] = ev[1]; L[3 * NTHR] = l3;
        L[4 * NTHR] = ev[2]; L[5 * NTHR] = l5;   L[6 * NTHR] = l6;    L[7 * NTHR] = l7;
        L[8 * NTHR] = ev[3]; L[9 * NTHR] = l9;   L[10 * NTHR] = l10;  L[11 * NTHR] = l11;
        L[12 * NTHR] = l12;  L[13 * NTHR] = l13; L[14 * NTHR] = l14;  L[15 * NTHR] = l15;
        accE += l15;
    }

#define RED_ONE(var, slot) { \
        float v_ = (var); \
        v_ += __shfl_xor_sync(0xffffffffu, v_, 16); \
        v_ += __shfl_xor_sync(0xffffffffu, v_, 8);  \
        v_ += __shfl_xor_sync(0xffffffffu, v_, 4);  \
        v_ += __shfl_xor_sync(0xffffffffu, v_, 2);  \
        v_ += __shfl_xor_sync(0xffffffffu, v_, 1);  \
        if (lane == 0) wacc[warp][slot] = v_; }

    RED_ONE(accE, 45)

    // 2-nibble LUT gather for one 8-bit field (zero-conflict: bank = tid%32 always)
#define LOOKUP2(f) ( lutb[((f) & 15u) * NTHR] + lutb[(16 + (((f) >> 4) & 15u)) * NTHR] )

    // ======== merged tap pass: per tap compute value, reduce immediately ========
#define TAP3(i) { \
        unsigned fx = __funnelshift_r(xw0, xw1, i) & 0xFFu; \
        unsigned fy = __funnelshift_r(yw0, yw1, i) & 0xFFu; \
        unsigned fz = fx & fy; \
        float vx = LOOKUP2(fx); \
        float vy = LOOKUP2(fy); \
        float vz = LOOKUP2(fz); \
        RED_ONE(vx, i) \
        RED_ONE(vy, 15 + i) \
        RED_ONE(vz, 30 + i) }
    FOR15(TAP3)
#undef TAP3
#undef RED_ONE
    __syncthreads();

    if (tid < 46) {
        float s = 0.f;
#pragma unroll
        for (int w = 0; w < 16; w++) s += wacc[w][tid];
        fin[tid] = s;
    }
    __syncthreads();

    // ---- A[i][v] from (E, Ex, Ey, Exy) ----
    if (tid < NIV) {
        int i = tid >> 2, v = tid & 3;
        float E = fin[45], Ex = fin[i], Ey = fin[15 + i], Exy = fin[30 + i];
        A_s[tid] = (v == 3) ? Exy
                 : (v == 1) ? (Ex - Exy)
                 : (v == 2) ? (Ey - Exy)
                 : (E - Ex - Ey + Exy);
    }
    __syncthreads();

    // ---- out[c] = ob[c] + (WvWc*A)[c]/E ----
    if (tid < DC) {
        const float4* w4 = (const float4*)(g_WvWc + tid * NIV);
        float s = 0.f;
#pragma unroll
        for (int q = 0; q < NIV / 4; q++) {
            float4 f = w4[q];
            int j = q * 4;
            s += f.x * A_s[j] + f.y * A_s[j + 1] + f.z * A_s[j + 2] + f.w * A_s[j + 3];
        }
        out[(size_t)bid * DC + tid] = g_ob[tid] + s / fin[45];
    }
}

// ---------------- launch: ONE kernel, dynamic shared ----------------
// Inputs: tokens, emb, conv_w, conv_b, Wq, bq, Wk, bk, Wv, bv  (bk drops out of softmax)
extern "C" void kernel_launch(void* const* d_in, const int* in_sizes, int n_in,
                              void* d_out, int out_size) {
    const int*   tokens = (const int*)  d_in[0];
    const float* emb    = (const float*)d_in[1];
    const float* conv_w = (const float*)d_in[2];
    const float* conv_b = (const float*)d_in[3];
    const float* Wq     = (const float*)d_in[4];
    const float* bq     = (const float*)d_in[5];
    const float* Wk     = (const float*)d_in[6];
    const float* Wv     = (const float*)d_in[8];
    const float* bv     = (const float*)d_in[9];
    float*       out    = (float*)d_out;

    const size_t shbytes = (size_t)(3072 + 32 * NTHR) * sizeof(float);  // 76 KB
    cudaFuncSetAttribute(seq_all, cudaFuncAttributeMaxDynamicSharedMemorySize, (int)shbytes);
    seq_all<<<NBATCH, NTHR, shbytes>>>(tokens, emb, conv_w, conv_b, Wq, bq, Wk, Wv, bv, out);
}